// round 1
// baseline (speedup 1.0000x reference)
#include <cuda_runtime.h>
#include <math.h>

// Problem constants
#define BATCH   2
#define SEQ     2048
#define DMODEL  1024
#define NHEADS  16
#define HDIM    64
#define PLANE   32
#define M_ROWS  (BATCH*SEQ)          // 4096
#define ROPE_SCALE 0.006135923151542565f   // 2*pi/1024

// Scratch (device globals: allocation-free)
__device__ float g_q[BATCH*NHEADS*SEQ*HDIM];   // [B,H,N,D]
__device__ float g_k[BATCH*NHEADS*SEQ*HDIM];
__device__ float g_v[BATCH*NHEADS*SEQ*HDIM];
__device__ float g_o[BATCH*SEQ*DMODEL];        // [B,N,d]

// ---------------------------------------------------------------------------
// GEMM: C = A[M][K] * W[N][K]^T + bias, fp32, 128x128x8 tiles, TM=TN=8
// layout_bhnd: 0 -> C row-major [M][Nout]; 1 -> scatter into [B,H,N,D]
// ---------------------------------------------------------------------------
#define BM 128
#define BN 128
#define BKK 8
#define TM 8
#define TN 8

__global__ __launch_bounds__(256, 2)
void gemm_bias_kernel(const float* __restrict__ A,
                      const float* __restrict__ W,
                      const float* __restrict__ bias,
                      float* __restrict__ C,
                      int K, int Nout, int layout_bhnd)
{
    __shared__ float As[BKK][BM];
    __shared__ float Bs[BKK][BN];

    const int bm = blockIdx.y * BM;
    const int bn = blockIdx.x * BN;
    const int tid = threadIdx.x;
    const int tx = tid & 15;
    const int ty = tid >> 4;

    const int lrow = tid >> 1;          // 0..127
    const int lcol = (tid & 1) * 4;     // 0 or 4

    float acc[TM][TN];
#pragma unroll
    for (int i = 0; i < TM; i++)
#pragma unroll
        for (int j = 0; j < TN; j++) acc[i][j] = 0.f;

    const float* Arow = A + (size_t)(bm + lrow) * K + lcol;
    const float* Wrow = W + (size_t)(bn + lrow) * K + lcol;

    for (int k0 = 0; k0 < K; k0 += BKK) {
        float4 a4 = *(const float4*)(Arow + k0);
        float4 b4 = *(const float4*)(Wrow + k0);
        As[lcol + 0][lrow] = a4.x; As[lcol + 1][lrow] = a4.y;
        As[lcol + 2][lrow] = a4.z; As[lcol + 3][lrow] = a4.w;
        Bs[lcol + 0][lrow] = b4.x; Bs[lcol + 1][lrow] = b4.y;
        Bs[lcol + 2][lrow] = b4.z; Bs[lcol + 3][lrow] = b4.w;
        __syncthreads();

#pragma unroll
        for (int k = 0; k < BKK; k++) {
            float ra[TM], rb[TN];
            *(float4*)&ra[0] = *(const float4*)&As[k][ty * TM];
            *(float4*)&ra[4] = *(const float4*)&As[k][ty * TM + 4];
            *(float4*)&rb[0] = *(const float4*)&Bs[k][tx * TN];
            *(float4*)&rb[4] = *(const float4*)&Bs[k][tx * TN + 4];
#pragma unroll
            for (int i = 0; i < TM; i++)
#pragma unroll
                for (int j = 0; j < TN; j++)
                    acc[i][j] = fmaf(ra[i], rb[j], acc[i][j]);
        }
        __syncthreads();
    }

#pragma unroll
    for (int i = 0; i < TM; i++) {
        int m = bm + ty * TM + i;
#pragma unroll
        for (int j = 0; j < TN; j++) {
            int o = bn + tx * TN + j;
            float v = acc[i][j] + bias[o];
            if (layout_bhnd) {
                int b = m >> 11, n = m & 2047;
                int h = o >> 6,  dd = o & 63;
                C[(((size_t)(b * NHEADS + h)) * SEQ + n) * HDIM + dd] = v;
            } else {
                C[(size_t)m * Nout + o] = v;
            }
        }
    }
}

// ---------------------------------------------------------------------------
// RoPE (in place on [B,H,N,D]) — one thread per (row, pair)
// ---------------------------------------------------------------------------
__global__ void rope_kernel(float* __restrict__ X, const float* __restrict__ pos)
{
    int t = blockIdx.x * blockDim.x + threadIdx.x;
    const int total = BATCH * NHEADS * SEQ * (HDIM / 2);
    if (t >= total) return;
    int p = t & 31;              // pair index within head (32 pairs)
    int row = t >> 5;            // (b,h,n)
    int n = row & 2047;
    int bh = row >> 11;
    int b = bh >> 4;

    const float* pp = pos + ((size_t)(b * SEQ + n)) * 2;
    int plane = p >> 4;          // 0: x-plane, 1: y-plane
    int i = p & 15;              // freq index
    float inv_freq = __powf(10000.f, -(float)(2 * i) / 32.f);
    float ang = pp[plane] * ROPE_SCALE * inv_freq;
    float s, c;
    __sincosf(ang, &s, &c);

    float* xr = X + (size_t)row * HDIM + plane * PLANE + 2 * i;
    float x0 = xr[0], x1 = xr[1];
    xr[0] = x0 * c - x1 * s;
    xr[1] = x0 * s + x1 * c;
}

// ---------------------------------------------------------------------------
// Flash-style attention: block = 16 query rows, 128 threads (4 warps x 4 rows)
// Streams 64-key tiles of K,V through smem with online softmax.
// ---------------------------------------------------------------------------
#define TQ 16
#define TK 64

__global__ __launch_bounds__(128, 4)
void attn_kernel(const float* __restrict__ Q, const float* __restrict__ Kg,
                 const float* __restrict__ Vg, float* __restrict__ O)
{
    __shared__ float Qs[TQ][HDIM];
    __shared__ float Ks[TK][HDIM + 1];
    __shared__ float Vs[TK][HDIM + 1];
    __shared__ float Ps[4][TK];

    const int NT = SEQ / TQ;           // 128 query tiles per (b,h)
    int qt = blockIdx.x % NT;
    int bh = blockIdx.x / NT;
    int b = bh >> 4, h = bh & 15;

    int tid = threadIdx.x;
    int warp = tid >> 5, lane = tid & 31;

    const float* qbase = Q + ((size_t)bh * SEQ + qt * TQ) * HDIM;
    for (int i = tid; i < TQ * HDIM; i += 128)
        Qs[i >> 6][i & 63] = qbase[i];

    float m[4], l[4], a0[4], a1[4];
#pragma unroll
    for (int r = 0; r < 4; r++) { m[r] = -1e30f; l[r] = 0.f; a0[r] = 0.f; a1[r] = 0.f; }

    const float* kb = Kg + (size_t)bh * SEQ * HDIM;
    const float* vb = Vg + (size_t)bh * SEQ * HDIM;

    for (int kt = 0; kt < SEQ; kt += TK) {
        __syncthreads();
        const float* kbt = kb + (size_t)kt * HDIM;
        const float* vbt = vb + (size_t)kt * HDIM;
        for (int i = tid; i < TK * HDIM; i += 128) {
            int j = i >> 6, d = i & 63;
            Ks[j][d] = kbt[i];
            Vs[j][d] = vbt[i];
        }
        __syncthreads();

#pragma unroll
        for (int rr = 0; rr < 4; rr++) {
            int r = warp * 4 + rr;
            float s0 = 0.f, s1 = 0.f;
#pragma unroll 16
            for (int d = 0; d < HDIM; d++) {
                float qd = Qs[r][d];
                s0 = fmaf(qd, Ks[lane][d],      s0);
                s1 = fmaf(qd, Ks[lane + 32][d], s1);
            }
            s0 *= 0.125f; s1 *= 0.125f;        // 1/sqrt(64)

            float mt = fmaxf(s0, s1);
#pragma unroll
            for (int off = 16; off; off >>= 1)
                mt = fmaxf(mt, __shfl_xor_sync(0xffffffffu, mt, off));
            float mnew = fmaxf(m[rr], mt);
            float corr = __expf(m[rr] - mnew);
            float p0 = __expf(s0 - mnew);
            float p1 = __expf(s1 - mnew);
            float ls = p0 + p1;
#pragma unroll
            for (int off = 16; off; off >>= 1)
                ls += __shfl_xor_sync(0xffffffffu, ls, off);
            l[rr] = l[rr] * corr + ls;
            m[rr] = mnew;
            a0[rr] *= corr; a1[rr] *= corr;

            Ps[warp][lane] = p0;
            Ps[warp][lane + 32] = p1;
            __syncwarp();
#pragma unroll 16
            for (int j = 0; j < TK; j++) {
                float pj = Ps[warp][j];
                a0[rr] = fmaf(pj, Vs[j][lane],      a0[rr]);
                a1[rr] = fmaf(pj, Vs[j][lane + 32], a1[rr]);
            }
            __syncwarp();
        }
    }

#pragma unroll
    for (int rr = 0; rr < 4; rr++) {
        int r = warp * 4 + rr;
        int n = qt * TQ + r;
        float inv = 1.f / l[rr];
        size_t base = ((size_t)(b * SEQ + n)) * DMODEL + h * HDIM;
        O[base + lane]      = a0[rr] * inv;
        O[base + lane + 32] = a1[rr] * inv;
    }
}

// ---------------------------------------------------------------------------
extern "C" void kernel_launch(void* const* d_in, const int* in_sizes, int n_in,
                              void* d_out, int out_size)
{
    const float* x    = (const float*)d_in[0];
    const float* qpos = (const float*)d_in[1];
    const float* kpos = (const float*)d_in[2];
    const float* Wq = (const float*)d_in[3];
    const float* bq = (const float*)d_in[4];
    const float* Wk = (const float*)d_in[5];
    const float* bk = (const float*)d_in[6];
    const float* Wv = (const float*)d_in[7];
    const float* bv = (const float*)d_in[8];
    const float* Wo = (const float*)d_in[9];
    const float* bo = (const float*)d_in[10];
    float* out = (float*)d_out;

    float *pq, *pk, *pv, *po;
    cudaGetSymbolAddress((void**)&pq, g_q);
    cudaGetSymbolAddress((void**)&pk, g_k);
    cudaGetSymbolAddress((void**)&pv, g_v);
    cudaGetSymbolAddress((void**)&po, g_o);

    dim3 ggrid(DMODEL / BN, M_ROWS / BM);   // (8, 32)

    gemm_bias_kernel<<<ggrid, 256>>>(x, Wq, bq, pq, DMODEL, DMODEL, 1);
    gemm_bias_kernel<<<ggrid, 256>>>(x, Wk, bk, pk, DMODEL, DMODEL, 1);
    gemm_bias_kernel<<<ggrid, 256>>>(x, Wv, bv, pv, DMODEL, DMODEL, 1);

    int rope_threads = BATCH * NHEADS * SEQ * (HDIM / 2);
    rope_kernel<<<(rope_threads + 255) / 256, 256>>>(pq, qpos);
    rope_kernel<<<(rope_threads + 255) / 256, 256>>>(pk, kpos);

    attn_kernel<<<BATCH * NHEADS * (SEQ / TQ), 128>>>(pq, pk, pv, po);

    gemm_bias_kernel<<<ggrid, 256>>>(po, Wo, bo, out, DMODEL, DMODEL, 0);
}

// round 2
// speedup vs baseline: 6.5995x; 6.5995x over previous
#include <cuda_runtime.h>
#include <math.h>
#include <stdint.h>

#define BATCH   2
#define SEQ     2048
#define DMODEL  1024
#define NHEADS  16
#define HDIM    64
#define PLANE   32
#define M_ROWS  (BATCH*SEQ)
#define ROPE_SCALE 0.006135923151542565f   // 2*pi/1024

// Scratch (device globals: allocation-free)
__device__ float g_q[BATCH*NHEADS*SEQ*HDIM];   // [B,H,N,D]
__device__ float g_k[BATCH*NHEADS*SEQ*HDIM];
__device__ float g_v[BATCH*NHEADS*SEQ*HDIM];
__device__ float g_o[BATCH*SEQ*DMODEL];        // [B,N,d]

// ---------------------------------------------------------------------------
// helpers
// ---------------------------------------------------------------------------
__device__ __forceinline__ uint32_t f2tf(float x) {
    uint32_t u;
    asm("cvt.rna.tf32.f32 %0, %1;" : "=r"(u) : "f"(x));
    return u;
}

__device__ __forceinline__ void mma_tf32(float c[4],
                                         uint32_t a0, uint32_t a1, uint32_t a2, uint32_t a3,
                                         uint32_t b0, uint32_t b1)
{
    asm volatile(
        "mma.sync.aligned.m16n8k8.row.col.f32.tf32.tf32.f32 "
        "{%0,%1,%2,%3}, {%4,%5,%6,%7}, {%8,%9}, {%0,%1,%2,%3};\n"
        : "+f"(c[0]), "+f"(c[1]), "+f"(c[2]), "+f"(c[3])
        : "r"(a0), "r"(a1), "r"(a2), "r"(a3), "r"(b0), "r"(b1));
}

// ---------------------------------------------------------------------------
// tf32 MMA GEMM: C = A[M][K] * W[N][K]^T + bias
// BM=BN=128, BK=32, 256 threads (8 warps, 2x4), warp tile 64x32
// layout_bhnd: 0 -> row-major [M][1024]; 1 -> scatter to [B,H,N,D]
// ---------------------------------------------------------------------------
#define GBK 32

__global__ __launch_bounds__(256)
void gemm_tf32_kernel(const float* __restrict__ A,
                      const float* __restrict__ W,
                      const float* __restrict__ bias,
                      float* __restrict__ C,
                      int layout_bhnd)
{
    __shared__ uint32_t As[128][GBK + 4];
    __shared__ uint32_t Bs[128][GBK + 4];

    const int tid  = threadIdx.x;
    const int warp = tid >> 5;
    const int lane = tid & 31;
    const int wm = (warp & 1) * 64;    // warp M offset within CTA tile
    const int wn = (warp >> 1) * 32;   // warp N offset
    const int bm = blockIdx.y * 128;
    const int bn = blockIdx.x * 128;

    // global load mapping: 32 rows x 8 float4 per pass, 4 passes
    const int lr = tid >> 3;          // 0..31
    const int lc = (tid & 7) * 4;     // 0..28
    const float* Aptr = A + (size_t)(bm + lr) * DMODEL + lc;
    const float* Wptr = W + (size_t)(bn + lr) * DMODEL + lc;

    float4 pa[4], pb[4];
#pragma unroll
    for (int i = 0; i < 4; i++) {
        pa[i] = *(const float4*)(Aptr + (size_t)i * 32 * DMODEL);
        pb[i] = *(const float4*)(Wptr + (size_t)i * 32 * DMODEL);
    }

    float acc[4][4][4];
#pragma unroll
    for (int mt = 0; mt < 4; mt++)
#pragma unroll
        for (int nt = 0; nt < 4; nt++)
#pragma unroll
            for (int r = 0; r < 4; r++) acc[mt][nt][r] = 0.f;

    for (int k0 = 0; k0 < DMODEL; k0 += GBK) {
#pragma unroll
        for (int i = 0; i < 4; i++) {
            int r = lr + i * 32;
            As[r][lc + 0] = f2tf(pa[i].x); As[r][lc + 1] = f2tf(pa[i].y);
            As[r][lc + 2] = f2tf(pa[i].z); As[r][lc + 3] = f2tf(pa[i].w);
            Bs[r][lc + 0] = f2tf(pb[i].x); Bs[r][lc + 1] = f2tf(pb[i].y);
            Bs[r][lc + 2] = f2tf(pb[i].z); Bs[r][lc + 3] = f2tf(pb[i].w);
        }
        __syncthreads();

        if (k0 + GBK < DMODEL) {
#pragma unroll
            for (int i = 0; i < 4; i++) {
                pa[i] = *(const float4*)(Aptr + (size_t)i * 32 * DMODEL + k0 + GBK);
                pb[i] = *(const float4*)(Wptr + (size_t)i * 32 * DMODEL + k0 + GBK);
            }
        }

#pragma unroll
        for (int kk = 0; kk < GBK; kk += 8) {
            const int q = kk + (lane & 3);
            uint32_t af[4][4];
#pragma unroll
            for (int mt = 0; mt < 4; mt++) {
                int r0 = wm + mt * 16 + (lane >> 2);
                af[mt][0] = As[r0][q];
                af[mt][1] = As[r0 + 8][q];
                af[mt][2] = As[r0][q + 4];
                af[mt][3] = As[r0 + 8][q + 4];
            }
#pragma unroll
            for (int nt = 0; nt < 4; nt++) {
                int n0 = wn + nt * 8 + (lane >> 2);
                uint32_t b0 = Bs[n0][q];
                uint32_t b1 = Bs[n0][q + 4];
#pragma unroll
                for (int mt = 0; mt < 4; mt++)
                    mma_tf32(acc[mt][nt], af[mt][0], af[mt][1], af[mt][2], af[mt][3], b0, b1);
            }
        }
        __syncthreads();
    }

    // epilogue
#pragma unroll
    for (int mt = 0; mt < 4; mt++) {
        int r0 = bm + wm + mt * 16 + (lane >> 2);
        int r1 = r0 + 8;
#pragma unroll
        for (int nt = 0; nt < 4; nt++) {
            int c0 = bn + wn + nt * 8 + 2 * (lane & 3);
            float v00 = acc[mt][nt][0] + bias[c0];
            float v01 = acc[mt][nt][1] + bias[c0 + 1];
            float v10 = acc[mt][nt][2] + bias[c0];
            float v11 = acc[mt][nt][3] + bias[c0 + 1];
            if (layout_bhnd) {
                int h = c0 >> 6, dd = c0 & 63;
                {
                    int b = r0 >> 11, n = r0 & 2047;
                    float* p = &g_q[0]; // unused; direct compute below
                    (void)p;
                    size_t base = (((size_t)(b * NHEADS + h)) * SEQ + n) * HDIM + dd;
                    C[base] = v00; C[base + 1] = v01;
                }
                {
                    int b = r1 >> 11, n = r1 & 2047;
                    size_t base = (((size_t)(b * NHEADS + h)) * SEQ + n) * HDIM + dd;
                    C[base] = v10; C[base + 1] = v11;
                }
            } else {
                *(float2*)&C[(size_t)r0 * DMODEL + c0] = make_float2(v00, v01);
                *(float2*)&C[(size_t)r1 * DMODEL + c0] = make_float2(v10, v11);
            }
        }
    }
}

// ---------------------------------------------------------------------------
// RoPE (in place on [B,H,N,D])
// ---------------------------------------------------------------------------
__global__ void rope_kernel(float* __restrict__ X, const float* __restrict__ pos)
{
    int t = blockIdx.x * blockDim.x + threadIdx.x;
    const int total = BATCH * NHEADS * SEQ * (HDIM / 2);
    if (t >= total) return;
    int p = t & 31;
    int row = t >> 5;
    int n = row & 2047;
    int bh = row >> 11;
    int b = bh >> 4;

    const float* pp = pos + ((size_t)(b * SEQ + n)) * 2;
    int plane = p >> 4;
    int i = p & 15;
    float inv_freq = __powf(10000.f, -(float)(2 * i) / 32.f);
    float ang = pp[plane] * ROPE_SCALE * inv_freq;
    float s, c;
    __sincosf(ang, &s, &c);

    float* xr = X + (size_t)row * HDIM + plane * PLANE + 2 * i;
    float x0 = xr[0], x1 = xr[1];
    xr[0] = x0 * c - x1 * s;
    xr[1] = x0 * s + x1 * c;
}

// ---------------------------------------------------------------------------
// Flash attention with tf32 mma: 64 q-rows per CTA, 4 warps (16 rows each),
// 64-key tiles. Q fragments in registers; P routed through padded smem.
// ---------------------------------------------------------------------------
#define KS_STRIDE 68   // 64+4: (lane>>2)*stride + (lane&3) conflict-free
#define VS_STRIDE 72   // 64+8: (lane&3)*stride + (lane>>2) conflict-free

__global__ __launch_bounds__(128)
void attn_tf32_kernel(const float* __restrict__ Q, const float* __restrict__ Kg,
                      const float* __restrict__ Vg, float* __restrict__ O)
{
    extern __shared__ uint32_t sm[];
    uint32_t (*Ks)[KS_STRIDE] = (uint32_t(*)[KS_STRIDE])sm;
    uint32_t (*Vs)[VS_STRIDE] = (uint32_t(*)[VS_STRIDE])(sm + 64 * KS_STRIDE);
    uint32_t (*Ps)[KS_STRIDE] = (uint32_t(*)[KS_STRIDE])(sm + 64 * KS_STRIDE + 64 * VS_STRIDE);

    const int tid  = threadIdx.x;
    const int warp = tid >> 5;
    const int lane = tid & 31;
    const int qb = blockIdx.x & 31;   // 32 q-blocks per (b,h)
    const int bh = blockIdx.x >> 5;

    // Q fragments (scaled by 1/sqrt(64), tf32-rounded), rows warp*16..+15
    const float* qbase = Q + ((size_t)bh * SEQ + qb * 64) * HDIM;
    const int fr = warp * 16 + (lane >> 2);
    uint32_t qf[8][4];
#pragma unroll
    for (int ks = 0; ks < 8; ks++) {
        int c = ks * 8 + (lane & 3);
        qf[ks][0] = f2tf(qbase[(size_t)fr * 64 + c] * 0.125f);
        qf[ks][1] = f2tf(qbase[(size_t)(fr + 8) * 64 + c] * 0.125f);
        qf[ks][2] = f2tf(qbase[(size_t)fr * 64 + c + 4] * 0.125f);
        qf[ks][3] = f2tf(qbase[(size_t)(fr + 8) * 64 + c + 4] * 0.125f);
    }

    float m0 = -1e30f, m1 = -1e30f, l0 = 0.f, l1 = 0.f;
    float o[8][4];
#pragma unroll
    for (int nt = 0; nt < 8; nt++)
#pragma unroll
        for (int r = 0; r < 4; r++) o[nt][r] = 0.f;

    const float* kb = Kg + (size_t)bh * SEQ * HDIM;
    const float* vb = Vg + (size_t)bh * SEQ * HDIM;

    const int lr = tid >> 4;          // 0..7
    const int lc = (tid & 15) * 4;    // 0..60

    for (int kt = 0; kt < SEQ; kt += 64) {
        __syncthreads();
#pragma unroll
        for (int i = 0; i < 8; i++) {
            int r = lr + i * 8;
            float4 kv = *(const float4*)(kb + (size_t)(kt + r) * 64 + lc);
            float4 vv = *(const float4*)(vb + (size_t)(kt + r) * 64 + lc);
            Ks[r][lc + 0] = f2tf(kv.x); Ks[r][lc + 1] = f2tf(kv.y);
            Ks[r][lc + 2] = f2tf(kv.z); Ks[r][lc + 3] = f2tf(kv.w);
            Vs[r][lc + 0] = f2tf(vv.x); Vs[r][lc + 1] = f2tf(vv.y);
            Vs[r][lc + 2] = f2tf(vv.z); Vs[r][lc + 3] = f2tf(vv.w);
        }
        __syncthreads();

        // GEMM1: S = Qf * Ks^T   (16x64 per warp)
        float s[8][4];
#pragma unroll
        for (int nt = 0; nt < 8; nt++)
#pragma unroll
            for (int r = 0; r < 4; r++) s[nt][r] = 0.f;

#pragma unroll
        for (int ks = 0; ks < 8; ks++) {
            const int q = ks * 8 + (lane & 3);
#pragma unroll
            for (int nt = 0; nt < 8; nt++) {
                int n0 = nt * 8 + (lane >> 2);
                uint32_t b0 = Ks[n0][q];
                uint32_t b1 = Ks[n0][q + 4];
                mma_tf32(s[nt], qf[ks][0], qf[ks][1], qf[ks][2], qf[ks][3], b0, b1);
            }
        }

        // online softmax: rows r0 (c0,c1) and r1 (c2,c3)
        float rm0 = -1e30f, rm1 = -1e30f;
#pragma unroll
        for (int nt = 0; nt < 8; nt++) {
            rm0 = fmaxf(rm0, fmaxf(s[nt][0], s[nt][1]));
            rm1 = fmaxf(rm1, fmaxf(s[nt][2], s[nt][3]));
        }
        rm0 = fmaxf(rm0, __shfl_xor_sync(0xffffffffu, rm0, 1));
        rm0 = fmaxf(rm0, __shfl_xor_sync(0xffffffffu, rm0, 2));
        rm1 = fmaxf(rm1, __shfl_xor_sync(0xffffffffu, rm1, 1));
        rm1 = fmaxf(rm1, __shfl_xor_sync(0xffffffffu, rm1, 2));

        float mn0 = fmaxf(m0, rm0), mn1 = fmaxf(m1, rm1);
        float cr0 = __expf(m0 - mn0), cr1 = __expf(m1 - mn1);
        m0 = mn0; m1 = mn1;

        float sum0 = 0.f, sum1 = 0.f;
#pragma unroll
        for (int nt = 0; nt < 8; nt++) {
            s[nt][0] = __expf(s[nt][0] - mn0);
            s[nt][1] = __expf(s[nt][1] - mn0);
            s[nt][2] = __expf(s[nt][2] - mn1);
            s[nt][3] = __expf(s[nt][3] - mn1);
            sum0 += s[nt][0] + s[nt][1];
            sum1 += s[nt][2] + s[nt][3];
        }
        sum0 += __shfl_xor_sync(0xffffffffu, sum0, 1);
        sum0 += __shfl_xor_sync(0xffffffffu, sum0, 2);
        sum1 += __shfl_xor_sync(0xffffffffu, sum1, 1);
        sum1 += __shfl_xor_sync(0xffffffffu, sum1, 2);
        l0 = l0 * cr0 + sum0;
        l1 = l1 * cr1 + sum1;

#pragma unroll
        for (int nt = 0; nt < 8; nt++) {
            o[nt][0] *= cr0; o[nt][1] *= cr0;
            o[nt][2] *= cr1; o[nt][3] *= cr1;
        }

        // store P fragments to smem (per-warp region)
        const int pr = warp * 16 + (lane >> 2);
        const int pc = 2 * (lane & 3);
#pragma unroll
        for (int nt = 0; nt < 8; nt++) {
            uint2 lo = make_uint2(f2tf(s[nt][0]), f2tf(s[nt][1]));
            uint2 hi = make_uint2(f2tf(s[nt][2]), f2tf(s[nt][3]));
            *(uint2*)&Ps[pr][nt * 8 + pc]     = lo;
            *(uint2*)&Ps[pr + 8][nt * 8 + pc] = hi;
        }
        __syncwarp();

        // GEMM2: O += P * V
#pragma unroll
        for (int ks = 0; ks < 8; ks++) {
            int pq = ks * 8 + (lane & 3);
            uint32_t a0 = Ps[warp * 16 + (lane >> 2)][pq];
            uint32_t a1 = Ps[warp * 16 + (lane >> 2) + 8][pq];
            uint32_t a2 = Ps[warp * 16 + (lane >> 2)][pq + 4];
            uint32_t a3 = Ps[warp * 16 + (lane >> 2) + 8][pq + 4];
#pragma unroll
            for (int nt = 0; nt < 8; nt++) {
                int vcol = nt * 8 + (lane >> 2);
                uint32_t b0 = Vs[ks * 8 + (lane & 3)][vcol];
                uint32_t b1 = Vs[ks * 8 + (lane & 3) + 4][vcol];
                mma_tf32(o[nt], a0, a1, a2, a3, b0, b1);
            }
        }
        __syncwarp();
    }

    // finalize and write: O layout [B,N,DMODEL], head h at col h*64
    float inv0 = 1.f / l0, inv1 = 1.f / l1;
    int b = bh >> 4, h = bh & 15;
    int n0 = qb * 64 + warp * 16 + (lane >> 2);
    size_t base0 = ((size_t)(b * SEQ + n0)) * DMODEL + h * 64;
    size_t base1 = ((size_t)(b * SEQ + n0 + 8)) * DMODEL + h * 64;
#pragma unroll
    for (int nt = 0; nt < 8; nt++) {
        int c = nt * 8 + 2 * (lane & 3);
        *(float2*)&O[base0 + c] = make_float2(o[nt][0] * inv0, o[nt][1] * inv0);
        *(float2*)&O[base1 + c] = make_float2(o[nt][2] * inv1, o[nt][3] * inv1);
    }
}

// ---------------------------------------------------------------------------
extern "C" void kernel_launch(void* const* d_in, const int* in_sizes, int n_in,
                              void* d_out, int out_size)
{
    const float* x    = (const float*)d_in[0];
    const float* qpos = (const float*)d_in[1];
    const float* kpos = (const float*)d_in[2];
    const float* Wq = (const float*)d_in[3];
    const float* bq = (const float*)d_in[4];
    const float* Wk = (const float*)d_in[5];
    const float* bk = (const float*)d_in[6];
    const float* Wv = (const float*)d_in[7];
    const float* bv = (const float*)d_in[8];
    const float* Wo = (const float*)d_in[9];
    const float* bo = (const float*)d_in[10];
    float* out = (float*)d_out;

    float *pq, *pk, *pv, *po;
    cudaGetSymbolAddress((void**)&pq, g_q);
    cudaGetSymbolAddress((void**)&pk, g_k);
    cudaGetSymbolAddress((void**)&pv, g_v);
    cudaGetSymbolAddress((void**)&po, g_o);

    const int attn_smem = (64 * KS_STRIDE + 64 * VS_STRIDE + 64 * KS_STRIDE) * 4;
    cudaFuncSetAttribute(attn_tf32_kernel,
                         cudaFuncAttributeMaxDynamicSharedMemorySize, attn_smem);

    dim3 ggrid(DMODEL / 128, M_ROWS / 128);   // (8, 32)

    gemm_tf32_kernel<<<ggrid, 256>>>(x, Wq, bq, pq, 1);
    gemm_tf32_kernel<<<ggrid, 256>>>(x, Wk, bk, pk, 1);
    gemm_tf32_kernel<<<ggrid, 256>>>(x, Wv, bv, pv, 1);

    int rope_threads = BATCH * NHEADS * SEQ * (HDIM / 2);
    rope_kernel<<<(rope_threads + 255) / 256, 256>>>(pq, qpos);
    rope_kernel<<<(rope_threads + 255) / 256, 256>>>(pk, kpos);

    attn_tf32_kernel<<<BATCH * NHEADS * (SEQ / 64), 128, attn_smem>>>(pq, pk, pv, po);

    gemm_tf32_kernel<<<ggrid, 256>>>(po, Wo, bo, out, 0);
}